// round 11
// baseline (speedup 1.0000x reference)
#include <cuda_runtime.h>
#include <cstdint>

#define NN 100000
#define EE 600000
#define PP 100000
#define D  128

__device__ float g_hA[(size_t)NN * D];
__device__ float g_hB[(size_t)NN * D];
__device__ float g_agg[(size_t)NN * D];
__device__ float g_cnt[NN];

// packed f32x2 helpers
__device__ __forceinline__ void fma2(unsigned long long& acc,
                                     unsigned long long a, unsigned long long b) {
    asm("fma.rn.f32x2 %0, %1, %2, %0;" : "+l"(acc) : "l"(a), "l"(b));
}
__device__ __forceinline__ unsigned long long bcast2(float v) {
    unsigned long long r;
    asm("mov.b64 %0, {%1, %1};" : "=l"(r) : "f"(v));
    return r;
}
__device__ __forceinline__ void unpack2(unsigned long long p, float& lo, float& hi) {
    asm("mov.b64 {%0, %1}, %2;" : "=f"(lo), "=f"(hi) : "l"(p));
}
__device__ __forceinline__ void lds_v2u64(unsigned long long& a, unsigned long long& b,
                                          const void* p) {
    asm volatile("{ .reg .u64 t; cvta.to.shared.u64 t, %2; "
                 "ld.shared.v2.u64 {%0, %1}, [t]; }"
                 : "=l"(a), "=l"(b) : "l"(p));
}

// ---------------------------------------------------------------------------
// Edge scatter: agg[dst] += w * h[src], cnt[dst] += 1
// ---------------------------------------------------------------------------
__global__ void __launch_bounds__(256) edge_kernel(
    const int* __restrict__ src, const int* __restrict__ dst,
    const float* __restrict__ w, const float* __restrict__ h)
{
    int t = blockIdx.x * blockDim.x + threadIdx.x;
    int e = t >> 5;
    if (e >= EE) return;
    int lane = t & 31;
    int s = __ldg(src + e);
    int d = __ldg(dst + e);
    float we = __ldg(w + e);
    float4 v = __ldg((const float4*)(h + (size_t)s * D) + lane);
    v.x *= we; v.y *= we; v.z *= we; v.w *= we;
    float* a = g_agg + (size_t)d * D + lane * 4;
    asm volatile("red.global.add.v4.f32 [%0], {%1,%2,%3,%4};"
                 :: "l"(a), "f"(v.x), "f"(v.y), "f"(v.z), "f"(v.w) : "memory");
    if (lane == 0) atomicAdd(g_cnt + d, 1.0f);
}

// ---------------------------------------------------------------------------
// Fused SAGE node update: out = [h | agg/max(cnt,1)] @ [Wself;Wneigh] + b
// 128x128 tile, BK=16, 256 threads, 8x8 micro-tile, transposed-A smem,
// register prefetch, packed fma.rn.f32x2 inner loop (pairs over M).
// ---------------------------------------------------------------------------
#define BMN 128
#define BKN 16
#define APAD 132

__global__ void __launch_bounds__(256, 2) sage_node_kernel(
    const float* __restrict__ h_in,
    const float* __restrict__ Wself, const float* __restrict__ Wneigh,
    const float* __restrict__ bias,
    float* __restrict__ h_out, int do_relu)
{
    __shared__ float As[BKN][APAD];   // [k][m] transposed
    __shared__ float Bs[BKN][128];    // [k][n]
    __shared__ float rcp_s[BMN];

    int t = threadIdx.x;
    int row_blk = blockIdx.x * BMN;

    if (t < BMN) {
        int g = row_blk + t;
        float c = (g < NN) ? g_cnt[g] : 1.0f;
        rcp_s[t] = 1.0f / fmaxf(c, 1.0f);
    }

    int tm = t >> 4;        // 0..15
    int tn = t & 15;        // 0..15
    int r0 = tm * 8;
    int c0 = tn * 4;

    // acc2[c][rp]: c = 8 output cols (c0..c0+3, 64+c0..64+c0+3),
    // rp = 4 row-pairs (rows r0+2rp, r0+2rp+1) packed in f32x2
    unsigned long long acc2[8][4];
    #pragma unroll
    for (int c = 0; c < 8; c++)
        #pragma unroll
        for (int rp = 0; rp < 4; rp++) acc2[c][rp] = 0ULL;

    float4 pa[2], pb[2];
    int arow[2];

    auto load_tile = [&](int kb, float4* ra, float4* rb, int* rrow) {
        const float* Abase = (kb < 8) ? h_in : g_agg;
        int koff = (kb < 8) ? kb * BKN : kb * BKN - 128;
        #pragma unroll
        for (int i = 0; i < 2; i++) {
            int idx = t + i * 256;
            int ar = idx >> 2;
            int aq = idx & 3;
            rrow[i] = ar;
            int g = row_blk + ar;
            float4 v = make_float4(0.f, 0.f, 0.f, 0.f);
            if (g < NN)
                v = __ldg((const float4*)(Abase + (size_t)g * D + koff) + aq);
            ra[i] = v;
        }
        #pragma unroll
        for (int i = 0; i < 2; i++) {
            int idx = t + i * 256;
            int kk = idx >> 5;
            int j4 = idx & 31;
            int kg = kb * BKN + kk;
            const float* W = (kg < 128) ? Wself : Wneigh;
            rb[i] = __ldg((const float4*)(W + (size_t)(kg & 127) * D) + j4);
        }
    };

    load_tile(0, pa, pb, arow);
    __syncthreads();   // rcp_s ready

    #pragma unroll 1
    for (int kb = 0; kb < 16; kb++) {
        bool is_agg = (kb >= 8);
        #pragma unroll
        for (int i = 0; i < 2; i++) {
            int idx = t + i * 256;
            int aq = idx & 3;
            float sc = is_agg ? rcp_s[arow[i]] : 1.0f;
            As[aq * 4 + 0][arow[i]] = pa[i].x * sc;
            As[aq * 4 + 1][arow[i]] = pa[i].y * sc;
            As[aq * 4 + 2][arow[i]] = pa[i].z * sc;
            As[aq * 4 + 3][arow[i]] = pa[i].w * sc;
        }
        #pragma unroll
        for (int i = 0; i < 2; i++) {
            int idx = t + i * 256;
            int kk = idx >> 5;
            int j4 = idx & 31;
            *(float4*)&Bs[kk][j4 * 4] = pb[i];
        }
        __syncthreads();

        if (kb + 1 < 16) load_tile(kb + 1, pa, pb, arow);

        #pragma unroll
        for (int k = 0; k < BKN; k++) {
            unsigned long long a2[4];
            lds_v2u64(a2[0], a2[1], &As[k][r0]);
            lds_v2u64(a2[2], a2[3], &As[k][r0 + 4]);
            float4 b0 = *(float4*)&Bs[k][c0];
            float4 b1 = *(float4*)&Bs[k][64 + c0];
            unsigned long long b2[8];
            b2[0] = bcast2(b0.x); b2[1] = bcast2(b0.y);
            b2[2] = bcast2(b0.z); b2[3] = bcast2(b0.w);
            b2[4] = bcast2(b1.x); b2[5] = bcast2(b1.y);
            b2[6] = bcast2(b1.z); b2[7] = bcast2(b1.w);
            #pragma unroll
            for (int c = 0; c < 8; c++)
                #pragma unroll
                for (int rp = 0; rp < 4; rp++)
                    fma2(acc2[c][rp], a2[rp], b2[c]);
        }
        __syncthreads();
    }

    float4 bb0 = __ldg((const float4*)(bias + c0));
    float4 bb1 = __ldg((const float4*)(bias + 64 + c0));
    float bA[8] = {bb0.x, bb0.y, bb0.z, bb0.w, bb1.x, bb1.y, bb1.z, bb1.w};

    #pragma unroll
    for (int rp = 0; rp < 4; rp++) {
        float vlo[8], vhi[8];
        #pragma unroll
        for (int c = 0; c < 8; c++) {
            unpack2(acc2[c][rp], vlo[c], vhi[c]);
            vlo[c] += bA[c]; vhi[c] += bA[c];
            if (do_relu) { vlo[c] = fmaxf(vlo[c], 0.f); vhi[c] = fmaxf(vhi[c], 0.f); }
        }
        int glo = row_blk + r0 + 2 * rp;
        int ghi = glo + 1;
        if (glo < NN) {
            *(float4*)(h_out + (size_t)glo * D + c0) = make_float4(vlo[0], vlo[1], vlo[2], vlo[3]);
            *(float4*)(h_out + (size_t)glo * D + 64 + c0) = make_float4(vlo[4], vlo[5], vlo[6], vlo[7]);
        }
        if (ghi < NN) {
            *(float4*)(h_out + (size_t)ghi * D + c0) = make_float4(vhi[0], vhi[1], vhi[2], vhi[3]);
            *(float4*)(h_out + (size_t)ghi * D + 64 + c0) = make_float4(vhi[4], vhi[5], vhi[6], vhi[7]);
        }
    }
}

// ---------------------------------------------------------------------------
// Fused link predictor, one launch for pos+neg, f32x2 inner loops.
// ---------------------------------------------------------------------------
#define PB 782
#define ZT_PAD 132
#define PRED_BK 32
#define SMEM_PRED ((128 * ZT_PAD + PRED_BK * 128) * 4)

__global__ void __launch_bounds__(256, 2) pred_kernel(
    const float* __restrict__ h,
    const int* __restrict__ pos_a, const int* __restrict__ pos_b,
    const int* __restrict__ neg_a, const int* __restrict__ neg_b,
    const float* __restrict__ pw1, const float* __restrict__ pb1,
    const float* __restrict__ pw2, const float* __restrict__ pb2,
    const float* __restrict__ pw3, const float* __restrict__ pb3,
    float* __restrict__ out)
{
    extern __shared__ float sm[];
    float (*Zt)[ZT_PAD] = (float(*)[ZT_PAD])sm;
    float (*Bs)[128]    = (float(*)[128])(sm + 128 * ZT_PAD);

    int t = threadIdx.x;
    bool is_neg = blockIdx.x >= PB;
    int p0 = (is_neg ? (blockIdx.x - PB) : blockIdx.x) * 128;
    const int* ia = is_neg ? neg_a : pos_a;
    const int* ib = is_neg ? neg_b : pos_b;
    float* outp = out + (is_neg ? PP : 0);

    // --- stage 0: Zt[:, pair] = h[ia]*h[ib] ---
    {
        int zrow = t >> 1;
        int half = t & 1;
        int gp = p0 + zrow;
        bool valid = gp < PP;
        int sa = valid ? __ldg(ia + gp) : 0;
        int sb = valid ? __ldg(ib + gp) : 0;
        const float4* ha = (const float4*)(h + (size_t)sa * D) + half * 16;
        const float4* hb = (const float4*)(h + (size_t)sb * D) + half * 16;
        #pragma unroll
        for (int i = 0; i < 16; i++) {
            float4 va = __ldg(ha + i);
            float4 vb = __ldg(hb + i);
            int f = half * 64 + i * 4;
            Zt[f + 0][zrow] = va.x * vb.x;
            Zt[f + 1][zrow] = va.y * vb.y;
            Zt[f + 2][zrow] = va.z * vb.z;
            Zt[f + 3][zrow] = va.w * vb.w;
        }
    }

    int tm = t >> 4, tn = t & 15;
    int r0 = tm * 8, c0 = tn * 4;

    #pragma unroll 1
    for (int stage = 0; stage < 2; stage++) {
        const float* W = stage ? pw2 : pw1;
        const float* B = stage ? pb2 : pb1;

        unsigned long long acc2[8][4];
        #pragma unroll
        for (int c = 0; c < 8; c++)
            #pragma unroll
            for (int rp = 0; rp < 4; rp++) acc2[c][rp] = 0ULL;

        #pragma unroll 1
        for (int kb = 0; kb < 128; kb += PRED_BK) {
            __syncthreads();
            #pragma unroll
            for (int i = 0; i < 4; i++) {
                int idx = t + i * 256;
                int kk = idx >> 5;
                int j4 = idx & 31;
                *(float4*)&Bs[kk][j4 * 4] =
                    __ldg((const float4*)(W + (size_t)(kb + kk) * D) + j4);
            }
            __syncthreads();

            #pragma unroll
            for (int k = 0; k < PRED_BK; k++) {
                unsigned long long a2[4];
                lds_v2u64(a2[0], a2[1], &Zt[kb + k][r0]);
                lds_v2u64(a2[2], a2[3], &Zt[kb + k][r0 + 4]);
                float4 b0 = *(float4*)&Bs[k][c0];
                float4 b1 = *(float4*)&Bs[k][64 + c0];
                unsigned long long b2[8];
                b2[0] = bcast2(b0.x); b2[1] = bcast2(b0.y);
                b2[2] = bcast2(b0.z); b2[3] = bcast2(b0.w);
                b2[4] = bcast2(b1.x); b2[5] = bcast2(b1.y);
                b2[6] = bcast2(b1.z); b2[7] = bcast2(b1.w);
                #pragma unroll
                for (int c = 0; c < 8; c++)
                    #pragma unroll
                    for (int rp = 0; rp < 4; rp++)
                        fma2(acc2[c][rp], a2[rp], b2[c]);
            }
        }

        float4 bb0 = __ldg((const float4*)(B + c0));
        float4 bb1 = __ldg((const float4*)(B + 64 + c0));
        float bA[8] = {bb0.x, bb0.y, bb0.z, bb0.w, bb1.x, bb1.y, bb1.z, bb1.w};
        __syncthreads();   // everyone done reading Zt
        #pragma unroll
        for (int rp = 0; rp < 4; rp++) {
            #pragma unroll
            for (int c = 0; c < 8; c++) {
                float lo, hi;
                unpack2(acc2[c][rp], lo, hi);
                lo = fmaxf(lo + bA[c], 0.f);
                hi = fmaxf(hi + bA[c], 0.f);
                int col = (c < 4) ? (c0 + c) : (64 + c0 + c - 4);
                Zt[col][r0 + 2 * rp] = lo;
                Zt[col][r0 + 2 * rp + 1] = hi;
            }
        }
        __syncthreads();
    }

    // --- final: out = Zt^T @ pw3 + pb3 ---
    {
        int rr = t >> 1;
        int part = t & 1;
        float s = 0.f;
        #pragma unroll
        for (int j = 0; j < 64; j++) {
            int k = part * 64 + j;
            s += Zt[k][rr] * __ldg(pw3 + k);
        }
        s += __shfl_xor_sync(0xffffffffu, s, 1);
        if (part == 0 && p0 + rr < PP)
            outp[p0 + rr] = s + __ldg(pb3);
    }
}

// ---------------------------------------------------------------------------
extern "C" void kernel_launch(void* const* d_in, const int* in_sizes, int n_in,
                              void* d_out, int out_size)
{
    const float* x     = (const float*)d_in[0];
    const int* src[3]  = {(const int*)d_in[1], (const int*)d_in[4], (const int*)d_in[7]};
    const int* dst[3]  = {(const int*)d_in[2], (const int*)d_in[5], (const int*)d_in[8]};
    const float* w[3]  = {(const float*)d_in[3], (const float*)d_in[6], (const float*)d_in[9]};
    const int* pos_src = (const int*)d_in[10];
    const int* pos_dst = (const int*)d_in[11];
    const int* neg_src = (const int*)d_in[12];
    const int* neg_dst = (const int*)d_in[13];
    const float* Wself[3]  = {(const float*)d_in[14], (const float*)d_in[17], (const float*)d_in[20]};
    const float* Wneigh[3] = {(const float*)d_in[15], (const float*)d_in[18], (const float*)d_in[21]};
    const float* bvec[3]   = {(const float*)d_in[16], (const float*)d_in[19], (const float*)d_in[22]};
    const float* pw1 = (const float*)d_in[23];
    const float* pb1 = (const float*)d_in[24];
    const float* pw2 = (const float*)d_in[25];
    const float* pb2 = (const float*)d_in[26];
    const float* pw3 = (const float*)d_in[27];
    const float* pb3 = (const float*)d_in[28];

    float* out = (float*)d_out;
    float* h_final = out + 2 * PP;

    void *agg_p, *cnt_p, *hA_p, *hB_p;
    cudaGetSymbolAddress(&agg_p, g_agg);
    cudaGetSymbolAddress(&cnt_p, g_cnt);
    cudaGetSymbolAddress(&hA_p, g_hA);
    cudaGetSymbolAddress(&hB_p, g_hB);
    float* hA = (float*)hA_p;
    float* hB = (float*)hB_p;

    static bool attr_set = false;
    if (!attr_set) {
        cudaFuncSetAttribute(pred_kernel, cudaFuncAttributeMaxDynamicSharedMemorySize, SMEM_PRED);
        attr_set = true;
    }

    const int edge_blocks = (EE * 32 + 255) / 256;
    const int node_blocks = (NN + BMN - 1) / BMN;

    const float* layer_in[3]  = {x, hA, hB};
    float*       layer_out[3] = {hA, hB, h_final};

    for (int l = 0; l < 3; l++) {
        cudaMemsetAsync(agg_p, 0, (size_t)NN * D * sizeof(float));
        cudaMemsetAsync(cnt_p, 0, (size_t)NN * sizeof(float));
        edge_kernel<<<edge_blocks, 256>>>(src[l], dst[l], w[l], layer_in[l]);
        sage_node_kernel<<<node_blocks, 256>>>(layer_in[l], Wself[l], Wneigh[l],
                                               bvec[l], layer_out[l], l < 2 ? 1 : 0);
    }

    pred_kernel<<<2 * PB, 256, SMEM_PRED>>>(h_final, pos_src, pos_dst,
        neg_src, neg_dst, pw1, pb1, pw2, pb2, pw3, pb3, out);
}

// round 12
// speedup vs baseline: 1.2819x; 1.2819x over previous
#include <cuda_runtime.h>
#include <cuda_bf16.h>
#include <cstdint>

#define NN 100000
#define EE 600000
#define PP 100000
#define D  128

__device__ float g_hA[(size_t)NN * D];
__device__ float g_hB[(size_t)NN * D];
__device__ float g_agg[(size_t)NN * D];
__device__ float g_cnt[NN];
__device__ unsigned short g_bt_hi[128 * 256];   // BT[n][k] bf16 hi
__device__ unsigned short g_bt_lo[128 * 256];   // BT[n][k] bf16 lo

// ---------------------------------------------------------------------------
// PTX helpers
// ---------------------------------------------------------------------------
__device__ __forceinline__ uint32_t smem_u32(const void* p) {
    uint32_t a;
    asm("{ .reg .u64 t; cvta.to.shared.u64 t, %1; cvt.u32.u64 %0, t; }"
        : "=r"(a) : "l"(p));
    return a;
}
__device__ __forceinline__ void ldsm_x4(uint32_t& r0, uint32_t& r1,
                                        uint32_t& r2, uint32_t& r3, uint32_t addr) {
    asm volatile("ldmatrix.sync.aligned.m8n8.x4.shared.b16 {%0,%1,%2,%3}, [%4];"
                 : "=r"(r0), "=r"(r1), "=r"(r2), "=r"(r3) : "r"(addr));
}
__device__ __forceinline__ void ldsm_x2(uint32_t& r0, uint32_t& r1, uint32_t addr) {
    asm volatile("ldmatrix.sync.aligned.m8n8.x2.shared.b16 {%0,%1}, [%2];"
                 : "=r"(r0), "=r"(r1) : "r"(addr));
}
__device__ __forceinline__ void mma16816(float* d, const uint32_t* a, const uint32_t* b) {
    asm volatile(
        "mma.sync.aligned.m16n8k16.row.col.f32.bf16.bf16.f32 "
        "{%0,%1,%2,%3}, {%4,%5,%6,%7}, {%8,%9}, {%0,%1,%2,%3};"
        : "+f"(d[0]), "+f"(d[1]), "+f"(d[2]), "+f"(d[3])
        : "r"(a[0]), "r"(a[1]), "r"(a[2]), "r"(a[3]), "r"(b[0]), "r"(b[1]));
}
// split float4 into packed bf16 hi / lo (2x uint32 each)
__device__ __forceinline__ void split4(const float4& v, uint2& hi, uint2& lo) {
    __nv_bfloat162 h0 = __floats2bfloat162_rn(v.x, v.y);
    __nv_bfloat162 h1 = __floats2bfloat162_rn(v.z, v.w);
    float2 f0 = __bfloat1622float2(h0);
    float2 f1 = __bfloat1622float2(h1);
    __nv_bfloat162 l0 = __floats2bfloat162_rn(v.x - f0.x, v.y - f0.y);
    __nv_bfloat162 l1 = __floats2bfloat162_rn(v.z - f1.x, v.w - f1.y);
    hi = make_uint2(*(uint32_t*)&h0, *(uint32_t*)&h1);
    lo = make_uint2(*(uint32_t*)&l0, *(uint32_t*)&l1);
}

// ---------------------------------------------------------------------------
// Edge scatter: agg[dst] += w * h[src], cnt[dst] += 1
// ---------------------------------------------------------------------------
__global__ void __launch_bounds__(256) edge_kernel(
    const int* __restrict__ src, const int* __restrict__ dst,
    const float* __restrict__ w, const float* __restrict__ h)
{
    int t = blockIdx.x * blockDim.x + threadIdx.x;
    int e = t >> 5;
    if (e >= EE) return;
    int lane = t & 31;
    int s = __ldg(src + e);
    int d = __ldg(dst + e);
    float we = __ldg(w + e);
    float4 v = __ldg((const float4*)(h + (size_t)s * D) + lane);
    v.x *= we; v.y *= we; v.z *= we; v.w *= we;
    float* a = g_agg + (size_t)d * D + lane * 4;
    asm volatile("red.global.add.v4.f32 [%0], {%1,%2,%3,%4};"
                 :: "l"(a), "f"(v.x), "f"(v.y), "f"(v.z), "f"(v.w) : "memory");
    if (lane == 0) atomicAdd(g_cnt + d, 1.0f);
}

// ---------------------------------------------------------------------------
// Weight transpose + bf16 split: BT[n][k] (k<128: Wself, k>=128: Wneigh)
// ---------------------------------------------------------------------------
__global__ void __launch_bounds__(256) convw_kernel(
    const float* __restrict__ Wself, const float* __restrict__ Wneigh)
{
    int idx = blockIdx.x * 256 + threadIdx.x;    // 0..32767
    int n = idx >> 8, k = idx & 255;
    float v = (k < 128) ? __ldg(Wself + k * 128 + n)
                        : __ldg(Wneigh + (k - 128) * 128 + n);
    __nv_bfloat16 h = __float2bfloat16_rn(v);
    float r = v - __bfloat162float(h);
    __nv_bfloat16 l = __float2bfloat16_rn(r);
    g_bt_hi[idx] = __bfloat16_as_ushort(h);
    g_bt_lo[idx] = __bfloat16_as_ushort(l);
}

// ---------------------------------------------------------------------------
// Tensor-core SAGE node update (bf16 3-pass split, fp32 accum):
//   out = [h | agg/max(cnt,1)] @ [Wself;Wneigh] + b  (optional ReLU)
// CTA tile 128x128, 8 warps of 32x64 (m16n8k16), K = 8 chunks of 32.
// ---------------------------------------------------------------------------
#define SA 40   // smem row stride in halfwords (80B: 8 ldmatrix rows conflict-free)

__global__ void __launch_bounds__(256, 2) sage_node_mma(
    const float* __restrict__ h_in,
    const float* __restrict__ bias,
    float* __restrict__ h_out, int do_relu)
{
    __shared__ unsigned short Ahi[128 * SA], Alo[128 * SA];
    __shared__ unsigned short Bhi[128 * SA], Blo[128 * SA];
    __shared__ float rcp_s[128];

    int t = threadIdx.x;
    int lane = t & 31;
    int wid = t >> 5;
    int row_blk = blockIdx.x * 128;

    if (t < 128) {
        int g = row_blk + t;
        float c = (g < NN) ? g_cnt[g] : 1.0f;
        rcp_s[t] = 1.0f / fmaxf(c, 1.0f);
    }
    __syncthreads();

    uint32_t ahi_b = smem_u32(Ahi), alo_b = smem_u32(Alo);
    uint32_t bhi_b = smem_u32(Bhi), blo_b = smem_u32(Blo);

    int wm = wid & 3;       // M warp: rows wm*32
    int wn = wid >> 2;      // N warp: cols wn*64

    float acc[2][8][4];
    #pragma unroll
    for (int mt = 0; mt < 2; mt++)
        #pragma unroll
        for (int nt = 0; nt < 8; nt++)
            #pragma unroll
            for (int i = 0; i < 4; i++) acc[mt][nt][i] = 0.f;

    #pragma unroll 1
    for (int kb = 0; kb < 8; kb++) {
        // ---- A chunk: convert 128 rows x 32 k of (h | agg*rcp) into hi/lo ----
        const float* Ab = (kb < 4) ? h_in : g_agg;
        int koff = (kb & 3) * 32;
        bool isagg = (kb >= 4);
        #pragma unroll
        for (int i = 0; i < 4; i++) {
            int idx = t + i * 256;
            int row = idx >> 3, q = idx & 7;
            int g = row_blk + row;
            float4 v = make_float4(0.f, 0.f, 0.f, 0.f);
            if (g < NN) v = __ldg((const float4*)(Ab + (size_t)g * D + koff) + q);
            if (isagg) { float rc = rcp_s[row]; v.x *= rc; v.y *= rc; v.z *= rc; v.w *= rc; }
            uint2 hi, lo;
            split4(v, hi, lo);
            *(uint2*)&Ahi[row * SA + q * 4] = hi;
            *(uint2*)&Alo[row * SA + q * 4] = lo;
        }
        // ---- B chunk: copy pre-transposed bf16 BT rows ----
        #pragma unroll
        for (int i = 0; i < 2; i++) {
            int idx = t + i * 256;
            int n = idx >> 2, kq = idx & 3;
            uint4 vh = __ldg((const uint4*)(g_bt_hi + n * 256 + kb * 32 + kq * 8));
            uint4 vl = __ldg((const uint4*)(g_bt_lo + n * 256 + kb * 32 + kq * 8));
            *(uint4*)&Bhi[n * SA + kq * 8] = vh;
            *(uint4*)&Blo[n * SA + kq * 8] = vl;
        }
        __syncthreads();

        // ---- MMA: 2 k-steps of 16 ----
        #pragma unroll
        for (int kc = 0; kc < 2; kc++) {
            int k0 = kc * 16;
            // B fragments (hi + lo) for 8 n-tiles
            uint32_t bh[8][2], bl[8][2];
            int brow = wn * 64 + (lane & 7);
            int bcol = k0 + ((lane & 8) ? 8 : 0);
            #pragma unroll
            for (int nt = 0; nt < 8; nt++) {
                uint32_t boff = (uint32_t)((brow + nt * 8) * SA + bcol) * 2;
                ldsm_x2(bh[nt][0], bh[nt][1], bhi_b + boff);
                ldsm_x2(bl[nt][0], bl[nt][1], blo_b + boff);
            }
            // A hi fragments
            uint32_t a[2][4];
            int arow = wm * 32 + (lane & 15);
            int acol = k0 + ((lane & 16) ? 8 : 0);
            #pragma unroll
            for (int mt = 0; mt < 2; mt++)
                ldsm_x4(a[mt][0], a[mt][1], a[mt][2], a[mt][3],
                        ahi_b + (uint32_t)((arow + mt * 16) * SA + acol) * 2);
            // pass 1: hi*hi  pass 2: hi*lo
            #pragma unroll
            for (int mt = 0; mt < 2; mt++)
                #pragma unroll
                for (int nt = 0; nt < 8; nt++)
                    mma16816(acc[mt][nt], a[mt], bh[nt]);
            #pragma unroll
            for (int mt = 0; mt < 2; mt++)
                #pragma unroll
                for (int nt = 0; nt < 8; nt++)
                    mma16816(acc[mt][nt], a[mt], bl[nt]);
            // pass 3: lo*hi
            #pragma unroll
            for (int mt = 0; mt < 2; mt++)
                ldsm_x4(a[mt][0], a[mt][1], a[mt][2], a[mt][3],
                        alo_b + (uint32_t)((arow + mt * 16) * SA + acol) * 2);
            #pragma unroll
            for (int mt = 0; mt < 2; mt++)
                #pragma unroll
                for (int nt = 0; nt < 8; nt++)
                    mma16816(acc[mt][nt], a[mt], bh[nt]);
        }
        __syncthreads();
    }

    // ---- epilogue ----
    int g8 = lane >> 2, tig = lane & 3;
    #pragma unroll
    for (int mt = 0; mt < 2; mt++) {
        int r = row_blk + wm * 32 + mt * 16 + g8;
        #pragma unroll
        for (int nt = 0; nt < 8; nt++) {
            int c = wn * 64 + nt * 8 + tig * 2;
            float2 bb = __ldg((const float2*)(bias + c));
            float o0 = acc[mt][nt][0] + bb.x;
            float o1 = acc[mt][nt][1] + bb.y;
            float o2 = acc[mt][nt][2] + bb.x;
            float o3 = acc[mt][nt][3] + bb.y;
            if (do_relu) {
                o0 = fmaxf(o0, 0.f); o1 = fmaxf(o1, 0.f);
                o2 = fmaxf(o2, 0.f); o3 = fmaxf(o3, 0.f);
            }
            if (r < NN)     *(float2*)(h_out + (size_t)r * D + c)       = make_float2(o0, o1);
            if (r + 8 < NN) *(float2*)(h_out + (size_t)(r + 8) * D + c) = make_float2(o2, o3);
        }
    }
}

// ---------------------------------------------------------------------------
// Fused link predictor (R3 scalar version — known good)
// ---------------------------------------------------------------------------
#define PB 782
#define ZT_PAD 132
#define PRED_BK 32
#define SMEM_PRED ((128 * ZT_PAD + PRED_BK * 128) * 4)

__global__ void __launch_bounds__(256, 2) pred_kernel(
    const float* __restrict__ h,
    const int* __restrict__ pos_a, const int* __restrict__ pos_b,
    const int* __restrict__ neg_a, const int* __restrict__ neg_b,
    const float* __restrict__ pw1, const float* __restrict__ pb1,
    const float* __restrict__ pw2, const float* __restrict__ pb2,
    const float* __restrict__ pw3, const float* __restrict__ pb3,
    float* __restrict__ out)
{
    extern __shared__ float sm[];
    float (*Zt)[ZT_PAD] = (float(*)[ZT_PAD])sm;
    float (*Bs)[128]    = (float(*)[128])(sm + 128 * ZT_PAD);

    int t = threadIdx.x;
    bool is_neg = blockIdx.x >= PB;
    int p0 = (is_neg ? (blockIdx.x - PB) : blockIdx.x) * 128;
    const int* ia = is_neg ? neg_a : pos_a;
    const int* ib = is_neg ? neg_b : pos_b;
    float* outp = out + (is_neg ? PP : 0);

    {
        int zrow = t >> 1;
        int half = t & 1;
        int gp = p0 + zrow;
        bool valid = gp < PP;
        int sa = valid ? __ldg(ia + gp) : 0;
        int sb = valid ? __ldg(ib + gp) : 0;
        const float4* ha = (const float4*)(h + (size_t)sa * D) + half * 16;
        const float4* hb = (const float4*)(h + (size_t)sb * D) + half * 16;
        #pragma unroll
        for (int i = 0; i < 16; i++) {
            float4 va = __ldg(ha + i);
            float4 vb = __ldg(hb + i);
            int f = half * 64 + i * 4;
            Zt[f + 0][zrow] = va.x * vb.x;
            Zt[f + 1][zrow] = va.y * vb.y;
            Zt[f + 2][zrow] = va.z * vb.z;
            Zt[f + 3][zrow] = va.w * vb.w;
        }
    }

    int tm = t >> 4, tn = t & 15;
    int r0 = tm * 8, c0 = tn * 4;

    #pragma unroll 1
    for (int stage = 0; stage < 2; stage++) {
        const float* W = stage ? pw2 : pw1;
        const float* B = stage ? pb2 : pb1;

        float acc[8][8];
        #pragma unroll
        for (int r = 0; r < 8; r++)
            #pragma unroll
            for (int c = 0; c < 8; c++) acc[r][c] = 0.f;

        #pragma unroll 1
        for (int kb = 0; kb < 128; kb += PRED_BK) {
            __syncthreads();
            #pragma unroll
            for (int i = 0; i < 4; i++) {
                int idx = t + i * 256;
                int kk = idx >> 5;
                int j4 = idx & 31;
                *(float4*)&Bs[kk][j4 * 4] =
                    __ldg((const float4*)(W + (size_t)(kb + kk) * D) + j4);
            }
            __syncthreads();

            #pragma unroll
            for (int k = 0; k < PRED_BK; k++) {
                float4 a0 = *(float4*)&Zt[kb + k][r0];
                float4 a1 = *(float4*)&Zt[kb + k][r0 + 4];
                float4 b0 = *(float4*)&Bs[k][c0];
                float4 b1 = *(float4*)&Bs[k][64 + c0];
                float av[8] = {a0.x, a0.y, a0.z, a0.w, a1.x, a1.y, a1.z, a1.w};
                #pragma unroll
                for (int r = 0; r < 8; r++) {
                    acc[r][0] += av[r] * b0.x; acc[r][1] += av[r] * b0.y;
                    acc[r][2] += av[r] * b0.z; acc[r][3] += av[r] * b0.w;
                    acc[r][4] += av[r] * b1.x; acc[r][5] += av[r] * b1.y;
                    acc[r][6] += av[r] * b1.z; acc[r][7] += av[r] * b1.w;
                }
            }
        }

        float4 bb0 = __ldg((const float4*)(B + c0));
        float4 bb1 = __ldg((const float4*)(B + 64 + c0));
        __syncthreads();
        #pragma unroll
        for (int r = 0; r < 8; r++) {
            float v[8];
            v[0] = fmaxf(acc[r][0] + bb0.x, 0.f);
            v[1] = fmaxf(acc[r][1] + bb0.y, 0.f);
            v[2] = fmaxf(acc[r][2] + bb0.z, 0.f);
            v[3] = fmaxf(acc[r][3] + bb0.w, 0.f);
            v[4] = fmaxf(acc[r][4] + bb1.x, 0.f);
            v[5] = fmaxf(acc[r][5] + bb1.y, 0.f);
            v[6] = fmaxf(acc[r][6] + bb1.z, 0.f);
            v[7] = fmaxf(acc[r][7] + bb1.w, 0.f);
            #pragma unroll
            for (int c = 0; c < 4; c++) {
                Zt[c0 + c][r0 + r] = v[c];
                Zt[64 + c0 + c][r0 + r] = v[4 + c];
            }
        }
        __syncthreads();
    }

    {
        int rr = t >> 1;
        int part = t & 1;
        float s = 0.f;
        #pragma unroll
        for (int j = 0; j < 64; j++) {
            int k = part * 64 + j;
            s += Zt[k][rr] * __ldg(pw3 + k);
        }
        s += __shfl_xor_sync(0xffffffffu, s, 1);
        if (part == 0 && p0 + rr < PP)
            outp[p0 + rr] = s + __ldg(pb3);
    }
}

// ---------------------------------------------------------------------------
extern "C" void kernel_launch(void* const* d_in, const int* in_sizes, int n_in,
                              void* d_out, int out_size)
{
    const float* x     = (const float*)d_in[0];
    const int* src[3]  = {(const int*)d_in[1], (const int*)d_in[4], (const int*)d_in[7]};
    const int* dst[3]  = {(const int*)d_in[2], (const int*)d_in[5], (const int*)d_in[8]};
    const float* w[3]  = {(const float*)d_in[3], (const float*)d_in[6], (const float*)d_in[9]};
    const int* pos_src = (const int*)d_in[10];
    const int* pos_dst = (const int*)d_in[11];
    const int* neg_src = (const int*)d_in[12];
    const int* neg_dst = (const int*)d_in[13];
    const float* Wself[3]  = {(const float*)d_in[14], (const float*)d_in[17], (const float*)d_in[20]};
    const float* Wneigh[3] = {(const float*)d_in[15], (const float*)d_in[18], (const float*)d_in[21]};
    const float* bvec[3]   = {(const float*)d_in[16], (const float*)d_in[19], (const float*)d_in[22]};
    const float* pw1 = (const float*)d_in[23];
    const float* pb1 = (const float*)d_in[24];
    const float* pw2 = (const float*)d_in[25];
    const float* pb2 = (const float*)d_in[26];
    const float* pw3 = (const float*)d_in[27];
    const float* pb3 = (const float*)d_in[28];

    float* out = (float*)d_out;
    float* h_final = out + 2 * PP;

    void *agg_p, *cnt_p, *hA_p, *hB_p;
    cudaGetSymbolAddress(&agg_p, g_agg);
    cudaGetSymbolAddress(&cnt_p, g_cnt);
    cudaGetSymbolAddress(&hA_p, g_hA);
    cudaGetSymbolAddress(&hB_p, g_hB);
    float* hA = (float*)hA_p;
    float* hB = (float*)hB_p;

    static bool attr_set = false;
    if (!attr_set) {
        cudaFuncSetAttribute(pred_kernel, cudaFuncAttributeMaxDynamicSharedMemorySize, SMEM_PRED);
        attr_set = true;
    }

    const int edge_blocks = (EE * 32 + 255) / 256;
    const int node_blocks = (NN + 127) / 128;

    const float* layer_in[3]  = {x, hA, hB};
    float*       layer_out[3] = {hA, hB, h_final};

    for (int l = 0; l < 3; l++) {
        cudaMemsetAsync(agg_p, 0, (size_t)NN * D * sizeof(float));
        cudaMemsetAsync(cnt_p, 0, (size_t)NN * sizeof(float));
        convw_kernel<<<128, 256>>>(Wself[l], Wneigh[l]);
        edge_kernel<<<edge_blocks, 256>>>(src[l], dst[l], w[l], layer_in[l]);
        sage_node_mma<<<node_blocks, 256>>>(layer_in[l], bvec[l],
                                            layer_out[l], l < 2 ? 1 : 0);
    }

    pred_kernel<<<2 * PB, 256, SMEM_PRED>>>(h_final, pos_src, pos_dst,
        neg_src, neg_dst, pw1, pb1, pw2, pb2, pw3, pb3, out);
}

// round 14
// speedup vs baseline: 1.5288x; 1.1926x over previous
#include <cuda_runtime.h>
#include <cuda_bf16.h>
#include <cstdint>

#define NN 100000
#define EE 600000
#define PP 100000
#define D  128

__device__ float g_hA[(size_t)NN * D];
__device__ float g_hB[(size_t)NN * D];
__device__ float g_agg[(size_t)NN * D];
__device__ float g_cnt[NN];
__device__ unsigned short g_bt_hi[128 * 256];     // node BT[n][k] bf16 hi
__device__ unsigned short g_bt_lo[128 * 256];     // node BT[n][k] bf16 lo
__device__ unsigned short g_pt_hi[2 * 128 * 128]; // pred PT[stage][n][k] hi
__device__ unsigned short g_pt_lo[2 * 128 * 128]; // pred PT[stage][n][k] lo

// ---------------------------------------------------------------------------
// PTX helpers
// ---------------------------------------------------------------------------
__device__ __forceinline__ uint32_t smem_u32(const void* p) {
    uint32_t a;
    asm("{ .reg .u64 t; cvta.to.shared.u64 t, %1; cvt.u32.u64 %0, t; }"
        : "=r"(a) : "l"(p));
    return a;
}
__device__ __forceinline__ void ldsm_x4(uint32_t& r0, uint32_t& r1,
                                        uint32_t& r2, uint32_t& r3, uint32_t addr) {
    asm volatile("ldmatrix.sync.aligned.m8n8.x4.shared.b16 {%0,%1,%2,%3}, [%4];"
                 : "=r"(r0), "=r"(r1), "=r"(r2), "=r"(r3) : "r"(addr));
}
__device__ __forceinline__ void ldsm_x2(uint32_t& r0, uint32_t& r1, uint32_t addr) {
    asm volatile("ldmatrix.sync.aligned.m8n8.x2.shared.b16 {%0,%1}, [%2];"
                 : "=r"(r0), "=r"(r1) : "r"(addr));
}
__device__ __forceinline__ void mma16816(float* d, const uint32_t* a, const uint32_t* b) {
    asm volatile(
        "mma.sync.aligned.m16n8k16.row.col.f32.bf16.bf16.f32 "
        "{%0,%1,%2,%3}, {%4,%5,%6,%7}, {%8,%9}, {%0,%1,%2,%3};"
        : "+f"(d[0]), "+f"(d[1]), "+f"(d[2]), "+f"(d[3])
        : "r"(a[0]), "r"(a[1]), "r"(a[2]), "r"(a[3]), "r"(b[0]), "r"(b[1]));
}
__device__ __forceinline__ void split4(const float4& v, uint2& hi, uint2& lo) {
    __nv_bfloat162 h0 = __floats2bfloat162_rn(v.x, v.y);
    __nv_bfloat162 h1 = __floats2bfloat162_rn(v.z, v.w);
    float2 f0 = __bfloat1622float2(h0);
    float2 f1 = __bfloat1622float2(h1);
    __nv_bfloat162 l0 = __floats2bfloat162_rn(v.x - f0.x, v.y - f0.y);
    __nv_bfloat162 l1 = __floats2bfloat162_rn(v.z - f1.x, v.w - f1.y);
    hi = make_uint2(*(uint32_t*)&h0, *(uint32_t*)&h1);
    lo = make_uint2(*(uint32_t*)&l0, *(uint32_t*)&l1);
}
__device__ __forceinline__ void split1(float v, unsigned short& hi, unsigned short& lo) {
    __nv_bfloat16 h = __float2bfloat16_rn(v);
    float r = v - __bfloat162float(h);
    __nv_bfloat16 l = __float2bfloat16_rn(r);
    hi = __bfloat16_as_ushort(h);
    lo = __bfloat16_as_ushort(l);
}

// ---------------------------------------------------------------------------
// Edge scatter: agg[dst] += w * h[src], cnt[dst] += 1
// ---------------------------------------------------------------------------
__global__ void __launch_bounds__(256) edge_kernel(
    const int* __restrict__ src, const int* __restrict__ dst,
    const float* __restrict__ w, const float* __restrict__ h)
{
    int t = blockIdx.x * blockDim.x + threadIdx.x;
    int e = t >> 5;
    if (e >= EE) return;
    int lane = t & 31;
    int s = __ldg(src + e);
    int d = __ldg(dst + e);
    float we = __ldg(w + e);
    float4 v = __ldg((const float4*)(h + (size_t)s * D) + lane);
    v.x *= we; v.y *= we; v.z *= we; v.w *= we;
    float* a = g_agg + (size_t)d * D + lane * 4;
    asm volatile("red.global.add.v4.f32 [%0], {%1,%2,%3,%4};"
                 :: "l"(a), "f"(v.x), "f"(v.y), "f"(v.z), "f"(v.w) : "memory");
    if (lane == 0) atomicAdd(g_cnt + d, 1.0f);
}

// ---------------------------------------------------------------------------
// Node weight transpose + split: BT[n][k] (k<128: Wself, k>=128: Wneigh)
// ---------------------------------------------------------------------------
__global__ void __launch_bounds__(256) convw_kernel(
    const float* __restrict__ Wself, const float* __restrict__ Wneigh)
{
    int idx = blockIdx.x * 256 + threadIdx.x;
    int n = idx >> 8, k = idx & 255;
    float v = (k < 128) ? __ldg(Wself + k * 128 + n)
                        : __ldg(Wneigh + (k - 128) * 128 + n);
    split1(v, g_bt_hi[idx], g_bt_lo[idx]);
}

// Pred weight transpose + split: PT[s][n][k] = pw_s[k][n]
__global__ void __launch_bounds__(256) convp_kernel(
    const float* __restrict__ pw1, const float* __restrict__ pw2)
{
    int idx = blockIdx.x * 256 + threadIdx.x;
    int s = idx >> 14;
    int r = idx & 16383;
    int n = r >> 7, k = r & 127;
    const float* W = s ? pw2 : pw1;
    float v = __ldg(W + k * 128 + n);
    split1(v, g_pt_hi[idx], g_pt_lo[idx]);
}

// ---------------------------------------------------------------------------
// Tensor-core SAGE node update (bf16 3-pass split, fp32 accum) — R12, unchanged
// ---------------------------------------------------------------------------
#define SA 40   // 32-k chunk row stride in halfwords

__global__ void __launch_bounds__(256, 2) sage_node_mma(
    const float* __restrict__ h_in,
    const float* __restrict__ bias,
    float* __restrict__ h_out, int do_relu)
{
    __shared__ unsigned short Ahi[128 * SA], Alo[128 * SA];
    __shared__ unsigned short Bhi[128 * SA], Blo[128 * SA];
    __shared__ float rcp_s[128];

    int t = threadIdx.x;
    int lane = t & 31;
    int wid = t >> 5;
    int row_blk = blockIdx.x * 128;

    if (t < 128) {
        int g = row_blk + t;
        float c = (g < NN) ? g_cnt[g] : 1.0f;
        rcp_s[t] = 1.0f / fmaxf(c, 1.0f);
    }
    __syncthreads();

    uint32_t ahi_b = smem_u32(Ahi), alo_b = smem_u32(Alo);
    uint32_t bhi_b = smem_u32(Bhi), blo_b = smem_u32(Blo);

    int wm = wid & 3;
    int wn = wid >> 2;

    float acc[2][8][4];
    #pragma unroll
    for (int mt = 0; mt < 2; mt++)
        #pragma unroll
        for (int nt = 0; nt < 8; nt++)
            #pragma unroll
            for (int i = 0; i < 4; i++) acc[mt][nt][i] = 0.f;

    #pragma unroll 1
    for (int kb = 0; kb < 8; kb++) {
        const float* Ab = (kb < 4) ? h_in : g_agg;
        int koff = (kb & 3) * 32;
        bool isagg = (kb >= 4);
        #pragma unroll
        for (int i = 0; i < 4; i++) {
            int idx = t + i * 256;
            int row = idx >> 3, q = idx & 7;
            int g = row_blk + row;
            float4 v = make_float4(0.f, 0.f, 0.f, 0.f);
            if (g < NN) v = __ldg((const float4*)(Ab + (size_t)g * D + koff) + q);
            if (isagg) { float rc = rcp_s[row]; v.x *= rc; v.y *= rc; v.z *= rc; v.w *= rc; }
            uint2 hi, lo;
            split4(v, hi, lo);
            *(uint2*)&Ahi[row * SA + q * 4] = hi;
            *(uint2*)&Alo[row * SA + q * 4] = lo;
        }
        #pragma unroll
        for (int i = 0; i < 2; i++) {
            int idx = t + i * 256;
            int n = idx >> 2, kq = idx & 3;
            uint4 vh = __ldg((const uint4*)(g_bt_hi + n * 256 + kb * 32 + kq * 8));
            uint4 vl = __ldg((const uint4*)(g_bt_lo + n * 256 + kb * 32 + kq * 8));
            *(uint4*)&Bhi[n * SA + kq * 8] = vh;
            *(uint4*)&Blo[n * SA + kq * 8] = vl;
        }
        __syncthreads();

        #pragma unroll
        for (int kc = 0; kc < 2; kc++) {
            int k0 = kc * 16;
            uint32_t bh[8][2], bl[8][2];
            int brow = wn * 64 + (lane & 7);
            int bcol = k0 + ((lane & 8) ? 8 : 0);
            #pragma unroll
            for (int nt = 0; nt < 8; nt++) {
                uint32_t boff = (uint32_t)((brow + nt * 8) * SA + bcol) * 2;
                ldsm_x2(bh[nt][0], bh[nt][1], bhi_b + boff);
                ldsm_x2(bl[nt][0], bl[nt][1], blo_b + boff);
            }
            uint32_t a[2][4];
            int arow = wm * 32 + (lane & 15);
            int acol = k0 + ((lane & 16) ? 8 : 0);
            #pragma unroll
            for (int mt = 0; mt < 2; mt++)
                ldsm_x4(a[mt][0], a[mt][1], a[mt][2], a[mt][3],
                        ahi_b + (uint32_t)((arow + mt * 16) * SA + acol) * 2);
            #pragma unroll
            for (int mt = 0; mt < 2; mt++)
                #pragma unroll
                for (int nt = 0; nt < 8; nt++)
                    mma16816(acc[mt][nt], a[mt], bh[nt]);
            #pragma unroll
            for (int mt = 0; mt < 2; mt++)
                #pragma unroll
                for (int nt = 0; nt < 8; nt++)
                    mma16816(acc[mt][nt], a[mt], bl[nt]);
            #pragma unroll
            for (int mt = 0; mt < 2; mt++)
                ldsm_x4(a[mt][0], a[mt][1], a[mt][2], a[mt][3],
                        alo_b + (uint32_t)((arow + mt * 16) * SA + acol) * 2);
            #pragma unroll
            for (int mt = 0; mt < 2; mt++)
                #pragma unroll
                for (int nt = 0; nt < 8; nt++)
                    mma16816(acc[mt][nt], a[mt], bh[nt]);
        }
        __syncthreads();
    }

    int g8 = lane >> 2, tig = lane & 3;
    #pragma unroll
    for (int mt = 0; mt < 2; mt++) {
        int r = row_blk + wm * 32 + mt * 16 + g8;
        #pragma unroll
        for (int nt = 0; nt < 8; nt++) {
            int c = wn * 64 + nt * 8 + tig * 2;
            float2 bb = __ldg((const float2*)(bias + c));
            float o0 = acc[mt][nt][0] + bb.x;
            float o1 = acc[mt][nt][1] + bb.y;
            float o2 = acc[mt][nt][2] + bb.x;
            float o3 = acc[mt][nt][3] + bb.y;
            if (do_relu) {
                o0 = fmaxf(o0, 0.f); o1 = fmaxf(o1, 0.f);
                o2 = fmaxf(o2, 0.f); o3 = fmaxf(o3, 0.f);
            }
            if (r < NN)     *(float2*)(h_out + (size_t)r * D + c)       = make_float2(o0, o1);
            if (r + 8 < NN) *(float2*)(h_out + (size_t)(r + 8) * D + c) = make_float2(o2, o3);
        }
    }
}

// ---------------------------------------------------------------------------
// Tensor-core link predictor: 128 pairs/block, full-K (128) smem tiles.
// Row stride SAP=136 halfwords (272B): ldmatrix rows hit 17r mod 8 = r mod 8
// distinct 16B groups — conflict-free. Dynamic smem 139 KB, 1 CTA/SM.
// ---------------------------------------------------------------------------
#define PB 782
#define SAP 136
#define PRED_TILE (128 * SAP)                 // halfwords per tile
#define SMEM_PRED (4 * PRED_TILE * 2)         // 139264 bytes

__global__ void __launch_bounds__(256, 1) pred_mma(
    const float* __restrict__ h,
    const int* __restrict__ pos_a, const int* __restrict__ pos_b,
    const int* __restrict__ neg_a, const int* __restrict__ neg_b,
    const float* __restrict__ pb1, const float* __restrict__ pb2,
    const float* __restrict__ pw3, const float* __restrict__ pb3,
    float* __restrict__ out)
{
    extern __shared__ unsigned short psm[];
    unsigned short* Ahi = psm;
    unsigned short* Alo = psm + PRED_TILE;
    unsigned short* Bhi = psm + 2 * PRED_TILE;
    unsigned short* Blo = psm + 3 * PRED_TILE;
    __shared__ float red[128][2];

    int t = threadIdx.x;
    int lane = t & 31;
    int wid = t >> 5;
    int wm = wid & 3;
    int wn = wid >> 2;

    bool is_neg = blockIdx.x >= PB;
    int p0 = (is_neg ? (blockIdx.x - PB) : blockIdx.x) * 128;
    const int* ia = is_neg ? neg_a : pos_a;
    const int* ib = is_neg ? neg_b : pos_b;
    float* outp = out + (is_neg ? PP : 0);

    uint32_t ahi_b = smem_u32(Ahi), alo_b = smem_u32(Alo);
    uint32_t bhi_b = smem_u32(Bhi), blo_b = smem_u32(Blo);

    // ---- stage 0: build Z = h[a]*h[b] -> Ahi/Alo (full K=128 per row) ----
    {
        int p = t >> 1;            // pair 0..127
        int half = t & 1;          // feature half (64 features each)
        int gp = p0 + p;
        bool valid = gp < PP;
        int sa = valid ? __ldg(ia + gp) : 0;
        int sb = valid ? __ldg(ib + gp) : 0;
        const float4* ha = (const float4*)(h + (size_t)sa * D) + half * 16;
        const float4* hb = (const float4*)(h + (size_t)sb * D) + half * 16;
        #pragma unroll
        for (int i = 0; i < 16; i += 2) {
            float4 va = __ldg(ha + i), va2 = __ldg(ha + i + 1);
            float4 vb = __ldg(hb + i), vb2 = __ldg(hb + i + 1);
            float4 z = make_float4(va.x * vb.x, va.y * vb.y, va.z * vb.z, va.w * vb.w);
            float4 z2 = make_float4(va2.x * vb2.x, va2.y * vb2.y, va2.z * vb2.z, va2.w * vb2.w);
            uint2 hi, lo, hi2, lo2;
            split4(z, hi, lo);
            split4(z2, hi2, lo2);
            int o = p * SAP + half * 64 + i * 4;   // halfword offset, 16B aligned (i even)
            *(uint4*)&Ahi[o] = make_uint4(hi.x, hi.y, hi2.x, hi2.y);
            *(uint4*)&Alo[o] = make_uint4(lo.x, lo.y, lo2.x, lo2.y);
        }
    }

    float acc[2][8][4];
    int g8 = lane >> 2, tig = lane & 3;

    #pragma unroll 1
    for (int stage = 0; stage < 2; stage++) {
        // load stage weights PT[stage] into Bhi/Blo (full K rows)
        const unsigned short* ph = g_pt_hi + stage * 16384;
        const unsigned short* pl = g_pt_lo + stage * 16384;
        #pragma unroll
        for (int i = 0; i < 8; i++) {
            int idx = t + i * 256;            // 0..2047 uint4s (128 n x 16 kq)
            int n = idx >> 4, kq = idx & 15;
            *(uint4*)&Bhi[n * SAP + kq * 8] = __ldg((const uint4*)(ph + n * 128) + kq);
            *(uint4*)&Blo[n * SAP + kq * 8] = __ldg((const uint4*)(pl + n * 128) + kq);
        }
        __syncthreads();   // A (stage0: Z; stage1: epilogue) + B ready

        #pragma unroll
        for (int mt = 0; mt < 2; mt++)
            #pragma unroll
            for (int nt = 0; nt < 8; nt++)
                #pragma unroll
                for (int i = 0; i < 4; i++) acc[mt][nt][i] = 0.f;

        #pragma unroll 1
        for (int kc = 0; kc < 8; kc++) {
            int k0 = kc * 16;
            uint32_t bh[8][2], bl[8][2];
            int brow = wn * 64 + (lane & 7);
            int bcol = k0 + ((lane & 8) ? 8 : 0);
            #pragma unroll
            for (int nt = 0; nt < 8; nt++) {
                uint32_t boff = (uint32_t)((brow + nt * 8) * SAP + bcol) * 2;
                ldsm_x2(bh[nt][0], bh[nt][1], bhi_b + boff);
                ldsm_x2(bl[nt][0], bl[nt][1], blo_b + boff);
            }
            uint32_t a[2][4];
            int arow = wm * 32 + (lane & 15);
            int acol = k0 + ((lane & 16) ? 8 : 0);
            #pragma unroll
            for (int mt = 0; mt < 2; mt++)
                ldsm_x4(a[mt][0], a[mt][1], a[mt][2], a[mt][3],
                        ahi_b + (uint32_t)((arow + mt * 16) * SAP + acol) * 2);
            #pragma unroll
            for (int mt = 0; mt < 2; mt++)
                #pragma unroll
                for (int nt = 0; nt < 8; nt++)
                    mma16816(acc[mt][nt], a[mt], bh[nt]);
            #pragma unroll
            for (int mt = 0; mt < 2; mt++)
                #pragma unroll
                for (int nt = 0; nt < 8; nt++)
                    mma16816(acc[mt][nt], a[mt], bl[nt]);
            #pragma unroll
            for (int mt = 0; mt < 2; mt++)
                ldsm_x4(a[mt][0], a[mt][1], a[mt][2], a[mt][3],
                        alo_b + (uint32_t)((arow + mt * 16) * SAP + acol) * 2);
            #pragma unroll
            for (int mt = 0; mt < 2; mt++)
                #pragma unroll
                for (int nt = 0; nt < 8; nt++)
                    mma16816(acc[mt][nt], a[mt], bh[nt]);
        }
        __syncthreads();   // all MMA reads of A and B done

        if (stage == 0) {
            // bias + relu, split, write back to Ahi/Alo
            #pragma unroll
            for (int mt = 0; mt < 2; mt++) {
                int r = wm * 32 + mt * 16 + g8;
                #pragma unroll
                for (int nt = 0; nt < 8; nt++) {
                    int c = wn * 64 + nt * 8 + tig * 2;
                    float2 bb = __ldg((const float2*)(pb1 + c));
                    float v0 = fmaxf(acc[mt][nt][0] + bb.x, 0.f);
                    float v1 = fmaxf(acc[mt][nt][1] + bb.y, 0.f);
                    float v2 = fmaxf(acc[mt][nt][2] + bb.x, 0.f);
                    float v3 = fmaxf(acc[mt][nt][3] + bb.y, 0.f);
                    unsigned short h0, l0, h1, l1, h2, l2, h3, l3;
                    split1(v0, h0, l0); split1(v1, h1, l1);
                    split1(v2, h2, l2); split1(v3, h3, l3);
                    Ahi[r * SAP + c] = h0;       Ahi[r * SAP + c + 1] = h1;
                    Alo[r * SAP + c] = l0;       Alo[r * SAP + c + 1] = l1;
                    Ahi[(r + 8) * SAP + c] = h2; Ahi[(r + 8) * SAP + c + 1] = h3;
                    Alo[(r + 8) * SAP + c] = l2; Alo[(r + 8) * SAP + c + 1] = l3;
                }
            }
            __syncthreads();   // writes visible before stage-1 MMA
        }
    }

    // ---- final: out[p] = relu(acc + pb2) . pw3 + pb3 ----
    {
        float s0 = 0.f, s1 = 0.f, s2 = 0.f, s3 = 0.f;
        #pragma unroll
        for (int nt = 0; nt < 8; nt++) {
            int c = wn * 64 + nt * 8 + tig * 2;
            float2 bb = __ldg((const float2*)(pb2 + c));
            float w0 = __ldg(pw3 + c);
            float w1 = __ldg(pw3 + c + 1);
            s0 += fmaxf(acc[0][nt][0] + bb.x, 0.f) * w0 + fmaxf(acc[0][nt][1] + bb.y, 0.f) * w1;
            s1 += fmaxf(acc[0][nt][2] + bb.x, 0.f) * w0 + fmaxf(acc[0][nt][3] + bb.y, 0.f) * w1;
            s2 += fmaxf(acc[1][nt][0] + bb.x, 0.f) * w0 + fmaxf(acc[1][nt][1] + bb.y, 0.f) * w1;
            s3 += fmaxf(acc[1][nt][2] + bb.x, 0.f) * w0 + fmaxf(acc[1][nt][3] + bb.y, 0.f) * w1;
        }
        #pragma unroll
        for (int d = 1; d < 4; d <<= 1) {
            s0 += __shfl_xor_sync(0xffffffffu, s0, d);
            s1 += __shfl_xor_sync(0xffffffffu, s1, d);
            s2 += __shfl_xor_sync(0xffffffffu, s2, d);
            s3 += __shfl_xor_sync(0xffffffffu, s3, d);
        }
        if (tig == 0) {
            int r = wm * 32 + g8;
            red[r][wn]      = s0;
            red[r + 8][wn]  = s1;
            red[r + 16][wn] = s2;
            red[r + 24][wn] = s3;
        }
    }
    __syncthreads();
    if (t < 128 && p0 + t < PP)
        outp[p0 + t] = red[t][0] + red[t][1] + __ldg(pb3);
}

// ---------------------------------------------------------------------------
extern "C" void kernel_launch(void* const* d_in, const int* in_sizes, int n_in,
                              void* d_out, int out_size)
{
    const float* x     = (const float*)d_in[0];
    const int* src[3]  = {(const int*)d_in[1], (const int*)d_in[4], (const int*)d_in[7]};
    const int* dst[3]  = {(const int*)d_in[2], (const int*)d_in[5], (const int*)d_in[8]};
    const float* w[3]  = {(const float*)d_in[3], (const float*)d_in[6], (const float*)d_in[9]};
    const int* pos_src = (const int*)d_in[10];
    const int* pos_dst = (const int*)d_in[11];
    const int* neg_src = (const int*)d_in[12];
    const int* neg_dst = (const int*)d_in[13];
    const float* Wself[3]  = {(const float*)d_in[14], (const float*)d_in[17], (const float*)d_in[20]};
    const float* Wneigh[3] = {(const float*)d_in[15], (const float*)d_in[18], (const float*)d_in[21]};
    const float* bvec[3]   = {(const float*)d_in[16], (const float*)d_in[19], (const float*)d_in[22]};
    const float* pw1 = (const float*)d_in[23];
    const float* pb1 = (const float*)d_in[24];
    const float* pw2 = (const float*)d_in[25];
    const float* pb2 = (const float*)d_in[26];
    const float* pw3 = (const float*)d_in[27];
    const float* pb3 = (const float*)d_in[28];

    float* out = (float*)d_out;
    float* h_final = out + 2 * PP;

    void *agg_p, *cnt_p, *hA_p, *hB_p;
    cudaGetSymbolAddress(&agg_p, g_agg);
    cudaGetSymbolAddress(&cnt_p, g_cnt);
    cudaGetSymbolAddress(&hA_p, g_hA);
    cudaGetSymbolAddress(&hB_p, g_hB);
    float* hA = (float*)hA_p;
    float* hB = (float*)hB_p;

    static bool attr_set = false;
    if (!attr_set) {
        cudaFuncSetAttribute(pred_mma, cudaFuncAttributeMaxDynamicSharedMemorySize, SMEM_PRED);
        attr_set = true;
    }

    const int edge_blocks = (EE * 32 + 255) / 256;
    const int node_blocks = (NN + 127) / 128;

    const float* layer_in[3]  = {x, hA, hB};
    float*       layer_out[3] = {hA, hB, h_final};

    convp_kernel<<<128, 256>>>(pw1, pw2);

    for (int l = 0; l < 3; l++) {
        cudaMemsetAsync(agg_p, 0, (size_t)NN * D * sizeof(float));
        cudaMemsetAsync(cnt_p, 0, (size_t)NN * sizeof(float));
        convw_kernel<<<128, 256>>>(Wself[l], Wneigh[l]);
        edge_kernel<<<edge_blocks, 256>>>(src[l], dst[l], w[l], layer_in[l]);
        sage_node_mma<<<node_blocks, 256>>>(layer_in[l], bvec[l],
                                            layer_out[l], l < 2 ? 1 : 0);
    }

    pred_mma<<<2 * PB, 256, SMEM_PRED>>>(h_final, pos_src, pos_dst, neg_src, neg_dst,
                                         pb1, pb2, pw3, pb3, out);
}

// round 15
// speedup vs baseline: 1.6206x; 1.0601x over previous
#include <cuda_runtime.h>
#include <cuda_bf16.h>
#include <cstdint>

#define NN 100000
#define EE 600000
#define PP 100000
#define D  128

__device__ float g_hA[(size_t)NN * D];
__device__ float g_hB[(size_t)NN * D];
__device__ float g_agg[(size_t)NN * D];     // zero-initialized; invariant: zero at entry
__device__ float g_cnt[NN];                 // same invariant
__device__ unsigned short g_bt_hi[128 * 256];
__device__ unsigned short g_bt_lo[128 * 256];
__device__ unsigned short g_pt_hi[2 * 128 * 128];
__device__ unsigned short g_pt_lo[2 * 128 * 128];

// ---------------------------------------------------------------------------
// PTX helpers
// ---------------------------------------------------------------------------
__device__ __forceinline__ uint32_t smem_u32(const void* p) {
    uint32_t a;
    asm("{ .reg .u64 t; cvta.to.shared.u64 t, %1; cvt.u32.u64 %0, t; }"
        : "=r"(a) : "l"(p));
    return a;
}
__device__ __forceinline__ void ldsm_x4(uint32_t& r0, uint32_t& r1,
                                        uint32_t& r2, uint32_t& r3, uint32_t addr) {
    asm volatile("ldmatrix.sync.aligned.m8n8.x4.shared.b16 {%0,%1,%2,%3}, [%4];"
                 : "=r"(r0), "=r"(r1), "=r"(r2), "=r"(r3) : "r"(addr));
}
__device__ __forceinline__ void ldsm_x2(uint32_t& r0, uint32_t& r1, uint32_t addr) {
    asm volatile("ldmatrix.sync.aligned.m8n8.x2.shared.b16 {%0,%1}, [%2];"
                 : "=r"(r0), "=r"(r1) : "r"(addr));
}
__device__ __forceinline__ void mma16816(float* d, const uint32_t* a, const uint32_t* b) {
    asm volatile(
        "mma.sync.aligned.m16n8k16.row.col.f32.bf16.bf16.f32 "
        "{%0,%1,%2,%3}, {%4,%5,%6,%7}, {%8,%9}, {%0,%1,%2,%3};"
        : "+f"(d[0]), "+f"(d[1]), "+f"(d[2]), "+f"(d[3])
        : "r"(a[0]), "r"(a[1]), "r"(a[2]), "r"(a[3]), "r"(b[0]), "r"(b[1]));
}
__device__ __forceinline__ void cp16(uint32_t dst, const void* src, uint32_t sz) {
    asm volatile("cp.async.cg.shared.global [%0], [%1], 16, %2;"
                 :: "r"(dst), "l"(src), "r"(sz) : "memory");
}
#define CP_COMMIT() asm volatile("cp.async.commit_group;" ::: "memory")
#define CP_WAIT0()  asm volatile("cp.async.wait_group 0;" ::: "memory")

__device__ __forceinline__ void split4(const float4& v, uint2& hi, uint2& lo) {
    __nv_bfloat162 h0 = __floats2bfloat162_rn(v.x, v.y);
    __nv_bfloat162 h1 = __floats2bfloat162_rn(v.z, v.w);
    float2 f0 = __bfloat1622float2(h0);
    float2 f1 = __bfloat1622float2(h1);
    __nv_bfloat162 l0 = __floats2bfloat162_rn(v.x - f0.x, v.y - f0.y);
    __nv_bfloat162 l1 = __floats2bfloat162_rn(v.z - f1.x, v.w - f1.y);
    hi = make_uint2(*(uint32_t*)&h0, *(uint32_t*)&h1);
    lo = make_uint2(*(uint32_t*)&l0, *(uint32_t*)&l1);
}
__device__ __forceinline__ void split1(float v, unsigned short& hi, unsigned short& lo) {
    __nv_bfloat16 h = __float2bfloat16_rn(v);
    float r = v - __bfloat162float(h);
    __nv_bfloat16 l = __float2bfloat16_rn(r);
    hi = __bfloat16_as_ushort(h);
    lo = __bfloat16_as_ushort(l);
}

// ---------------------------------------------------------------------------
// Edge scatter
// ---------------------------------------------------------------------------
__global__ void __launch_bounds__(256) edge_kernel(
    const int* __restrict__ src, const int* __restrict__ dst,
    const float* __restrict__ w, const float* __restrict__ h)
{
    int t = blockIdx.x * blockDim.x + threadIdx.x;
    int e = t >> 5;
    if (e >= EE) return;
    int lane = t & 31;
    int s = __ldg(src + e);
    int d = __ldg(dst + e);
    float we = __ldg(w + e);
    float4 v = __ldg((const float4*)(h + (size_t)s * D) + lane);
    v.x *= we; v.y *= we; v.z *= we; v.w *= we;
    float* a = g_agg + (size_t)d * D + lane * 4;
    asm volatile("red.global.add.v4.f32 [%0], {%1,%2,%3,%4};"
                 :: "l"(a), "f"(v.x), "f"(v.y), "f"(v.z), "f"(v.w) : "memory");
    if (lane == 0) atomicAdd(g_cnt + d, 1.0f);
}

// ---------------------------------------------------------------------------
// Weight conversions
// ---------------------------------------------------------------------------
__global__ void __launch_bounds__(256) convw_kernel(
    const float* __restrict__ Wself, const float* __restrict__ Wneigh)
{
    int idx = blockIdx.x * 256 + threadIdx.x;
    int n = idx >> 8, k = idx & 255;
    float v = (k < 128) ? __ldg(Wself + k * 128 + n)
                        : __ldg(Wneigh + (k - 128) * 128 + n);
    split1(v, g_bt_hi[idx], g_bt_lo[idx]);
}
__global__ void __launch_bounds__(256) convp_kernel(
    const float* __restrict__ pw1, const float* __restrict__ pw2)
{
    int idx = blockIdx.x * 256 + threadIdx.x;
    int s = idx >> 14;
    int r = idx & 16383;
    int n = r >> 7, k = r & 127;
    const float* W = s ? pw2 : pw1;
    float v = __ldg(W + k * 128 + n);
    split1(v, g_pt_hi[idx], g_pt_lo[idx]);
}

// ---------------------------------------------------------------------------
// Node update: cp.async double-buffered bf16 3-pass MMA pipeline.
// Dynamic smem layout (bytes):
//   AhiB[2]@0/10240, AloB[2]@20480/30720, BhiB[2]@40960/51200,
//   BloB[2]@61440/71680, raw@81920 (16KB)  => 98304 B total
// ---------------------------------------------------------------------------
#define SA 40
#define SMEM_NODE 98304

__global__ void __launch_bounds__(256, 2) sage_node_mma(
    const float* __restrict__ h_in,
    const float* __restrict__ bias,
    float* __restrict__ h_out, int do_relu)
{
    extern __shared__ char dsm[];
    __shared__ float rcp_s[128];

    int t = threadIdx.x;
    int lane = t & 31;
    int wid = t >> 5;
    int row_blk = blockIdx.x * 128;
    int wm = wid & 3;
    int wn = wid >> 2;

    uint32_t sb = smem_u32(dsm);
    uint32_t ahiB[2] = {sb,          sb + 10240};
    uint32_t aloB[2] = {sb + 20480,  sb + 30720};
    uint32_t bhiB[2] = {sb + 40960,  sb + 51200};
    uint32_t bloB[2] = {sb + 61440,  sb + 71680};
    uint32_t rawB    = sb + 81920;
    unsigned short* AhiP[2] = {(unsigned short*)dsm, (unsigned short*)(dsm + 10240)};
    unsigned short* AloP[2] = {(unsigned short*)(dsm + 20480), (unsigned short*)(dsm + 30720)};
    float* rawf = (float*)(dsm + 81920);

    auto issue_loads = [&](int kb, int b) {
        const float* Ab = (kb < 4) ? h_in : g_agg;
        int koff = (kb & 3) * 32;
        #pragma unroll
        for (int i = 0; i < 4; i++) {
            int idx = t + i * 256;
            int row = idx >> 3, q = idx & 7;
            int g = row_blk + row;
            int gc = (g < NN) ? g : (NN - 1);
            cp16(rawB + idx * 16, Ab + (size_t)gc * D + koff + q * 4,
                 (g < NN) ? 16u : 0u);
        }
        #pragma unroll
        for (int i = 0; i < 2; i++) {
            int idx = t + i * 256;
            int n = idx >> 2, kq = idx & 3;
            uint32_t doff = (uint32_t)(n * SA + kq * 8) * 2;
            const unsigned short* sh = g_bt_hi + n * 256 + kb * 32 + kq * 8;
            const unsigned short* sl = g_bt_lo + n * 256 + kb * 32 + kq * 8;
            cp16(bhiB[b] + doff, sh, 16);
            cp16(bloB[b] + doff, sl, 16);
        }
        CP_COMMIT();
    };
    auto convert = [&](int b, bool isagg) {
        #pragma unroll
        for (int i = 0; i < 4; i++) {
            int idx = t + i * 256;
            int row = idx >> 3, q = idx & 7;
            float4 v = *(float4*)(rawf + idx * 4);
            if (isagg) { float rc = rcp_s[row]; v.x *= rc; v.y *= rc; v.z *= rc; v.w *= rc; }
            uint2 hi, lo;
            split4(v, hi, lo);
            *(uint2*)&AhiP[b][row * SA + q * 4] = hi;
            *(uint2*)&AloP[b][row * SA + q * 4] = lo;
        }
    };

    issue_loads(0, 0);
    if (t < 128) {
        int g = row_blk + t;
        float c = (g < NN) ? g_cnt[g] : 1.0f;
        rcp_s[t] = 1.0f / fmaxf(c, 1.0f);
        if (g < NN) g_cnt[g] = 0.0f;     // restore zero invariant
    }
    CP_WAIT0();
    convert(0, false);
    __syncthreads();

    float acc[2][8][4];
    #pragma unroll
    for (int mt = 0; mt < 2; mt++)
        #pragma unroll
        for (int nt = 0; nt < 8; nt++)
            #pragma unroll
            for (int i = 0; i < 4; i++) acc[mt][nt][i] = 0.f;

    #pragma unroll 1
    for (int kb = 0; kb < 8; kb++) {
        int cur = kb & 1, nxt = cur ^ 1;
        if (kb < 7) issue_loads(kb + 1, nxt);

        #pragma unroll
        for (int kc = 0; kc < 2; kc++) {
            int k0 = kc * 16;
            uint32_t bh[8][2], bl[8][2];
            int brow = wn * 64 + (lane & 7);
            int bcol = k0 + ((lane & 8) ? 8 : 0);
            #pragma unroll
            for (int nt = 0; nt < 8; nt++) {
                uint32_t boff = (uint32_t)((brow + nt * 8) * SA + bcol) * 2;
                ldsm_x2(bh[nt][0], bh[nt][1], bhiB[cur] + boff);
                ldsm_x2(bl[nt][0], bl[nt][1], bloB[cur] + boff);
            }
            uint32_t a[2][4];
            int arow = wm * 32 + (lane & 15);
            int acol = k0 + ((lane & 16) ? 8 : 0);
            #pragma unroll
            for (int mt = 0; mt < 2; mt++)
                ldsm_x4(a[mt][0], a[mt][1], a[mt][2], a[mt][3],
                        ahiB[cur] + (uint32_t)((arow + mt * 16) * SA + acol) * 2);
            #pragma unroll
            for (int mt = 0; mt < 2; mt++)
                #pragma unroll
                for (int nt = 0; nt < 8; nt++)
                    mma16816(acc[mt][nt], a[mt], bh[nt]);
            #pragma unroll
            for (int mt = 0; mt < 2; mt++)
                #pragma unroll
                for (int nt = 0; nt < 8; nt++)
                    mma16816(acc[mt][nt], a[mt], bl[nt]);
            #pragma unroll
            for (int mt = 0; mt < 2; mt++)
                ldsm_x4(a[mt][0], a[mt][1], a[mt][2], a[mt][3],
                        aloB[cur] + (uint32_t)((arow + mt * 16) * SA + acol) * 2);
            #pragma unroll
            for (int mt = 0; mt < 2; mt++)
                #pragma unroll
                for (int nt = 0; nt < 8; nt++)
                    mma16816(acc[mt][nt], a[mt], bh[nt]);
        }

        if (kb < 7) {
            CP_WAIT0();
            convert(nxt, (kb + 1) >= 4);
        }
        __syncthreads();
    }

    // epilogue: bias + relu + store
    int g8 = lane >> 2, tig = lane & 3;
    #pragma unroll
    for (int mt = 0; mt < 2; mt++) {
        int r = row_blk + wm * 32 + mt * 16 + g8;
        #pragma unroll
        for (int nt = 0; nt < 8; nt++) {
            int c = wn * 64 + nt * 8 + tig * 2;
            float2 bb = __ldg((const float2*)(bias + c));
            float o0 = acc[mt][nt][0] + bb.x;
            float o1 = acc[mt][nt][1] + bb.y;
            float o2 = acc[mt][nt][2] + bb.x;
            float o3 = acc[mt][nt][3] + bb.y;
            if (do_relu) {
                o0 = fmaxf(o0, 0.f); o1 = fmaxf(o1, 0.f);
                o2 = fmaxf(o2, 0.f); o3 = fmaxf(o3, 0.f);
            }
            if (r < NN)     *(float2*)(h_out + (size_t)r * D + c)       = make_float2(o0, o1);
            if (r + 8 < NN) *(float2*)(h_out + (size_t)(r + 8) * D + c) = make_float2(o2, o3);
        }
    }
    // restore zero invariant on g_agg rows owned by this block
    float4 z4 = make_float4(0.f, 0.f, 0.f, 0.f);
    #pragma unroll
    for (int i = 0; i < 16; i++) {
        int idx = t + i * 256;          // 0..4095 float4s
        int row = idx >> 5, q = idx & 31;
        int g = row_blk + row;
        if (g < NN) *(float4*)(g_agg + (size_t)g * D + q * 4) = z4;
    }
}

// ---------------------------------------------------------------------------
// Link predictor: full-K A tiles (SAP=136), chunked B tiles (SA=40), 2 CTA/SM.
// Dynamic smem: Ahi@0 (34816B), Alo@34816, Bhi@69632 (10240B), Blo@79872 => 90112B
// ---------------------------------------------------------------------------
#define PB 782
#define SAP 136
#define SMEM_PRED 90112

__global__ void __launch_bounds__(256, 2) pred_mma(
    const float* __restrict__ h,
    const int* __restrict__ pos_a, const int* __restrict__ pos_b,
    const int* __restrict__ neg_a, const int* __restrict__ neg_b,
    const float* __restrict__ pb1, const float* __restrict__ pb2,
    const float* __restrict__ pw3, const float* __restrict__ pb3,
    float* __restrict__ out)
{
    extern __shared__ char dsm[];
    unsigned short* Ahi = (unsigned short*)dsm;
    unsigned short* Alo = (unsigned short*)(dsm + 34816);
    unsigned short* Bhi = (unsigned short*)(dsm + 69632);
    unsigned short* Blo = (unsigned short*)(dsm + 79872);
    __shared__ float red[128][2];

    int t = threadIdx.x;
    int lane = t & 31;
    int wid = t >> 5;
    int wm = wid & 3;
    int wn = wid >> 2;

    bool is_neg = blockIdx.x >= PB;
    int p0 = (is_neg ? (blockIdx.x - PB) : blockIdx.x) * 128;
    const int* ia = is_neg ? neg_a : pos_a;
    const int* ib = is_neg ? neg_b : pos_b;
    float* outp = out + (is_neg ? PP : 0);

    uint32_t ahi_b = smem_u32(Ahi), alo_b = smem_u32(Alo);
    uint32_t bhi_b = smem_u32(Bhi), blo_b = smem_u32(Blo);

    // stage 0: Z = h[a]*h[b] -> Ahi/Alo (full K)
    {
        int p = t >> 1;
        int half = t & 1;
        int gp = p0 + p;
        bool valid = gp < PP;
        int sa = valid ? __ldg(ia + gp) : 0;
        int sb = valid ? __ldg(ib + gp) : 0;
        const float4* ha = (const float4*)(h + (size_t)sa * D) + half * 16;
        const float4* hb = (const float4*)(h + (size_t)sb * D) + half * 16;
        #pragma unroll
        for (int i = 0; i < 16; i += 2) {
            float4 va = __ldg(ha + i), va2 = __ldg(ha + i + 1);
            float4 vb = __ldg(hb + i), vb2 = __ldg(hb + i + 1);
            float4 z = make_float4(va.x * vb.x, va.y * vb.y, va.z * vb.z, va.w * vb.w);
            float4 z2 = make_float4(va2.x * vb2.x, va2.y * vb2.y, va2.z * vb2.z, va2.w * vb2.w);
            uint2 hi, lo, hi2, lo2;
            split4(z, hi, lo);
            split4(z2, hi2, lo2);
            int o = p * SAP + half * 64 + i * 4;
            *(uint4*)&Ahi[o] = make_uint4(hi.x, hi.y, hi2.x, hi2.y);
            *(uint4*)&Alo[o] = make_uint4(lo.x, lo.y, lo2.x, lo2.y);
        }
    }

    float acc[2][8][4];
    int g8 = lane >> 2, tig = lane & 3;

    #pragma unroll 1
    for (int stage = 0; stage < 2; stage++) {
        const unsigned short* ph = g_pt_hi + stage * 16384;
        const unsigned short* pl = g_pt_lo + stage * 16384;

        #pragma unroll
        for (int mt = 0; mt < 2; mt++)
            #pragma unroll
            for (int nt = 0; nt < 8; nt++)
                #pragma unroll
                for (int i = 0; i < 4; i++) acc[mt][nt][i] = 0.f;

        #pragma unroll 1
        for (int kb = 0; kb < 4; kb++) {
            __syncthreads();   // previous MMA done with B buffer / A writes visible
            #pragma unroll
            for (int i = 0; i < 2; i++) {
                int idx = t + i * 256;       // 0..511
                int n = idx >> 2, kq = idx & 3;
                *(uint4*)&Bhi[n * SA + kq * 8] =
                    __ldg((const uint4*)(ph + n * 128 + kb * 32 + kq * 8));
                *(uint4*)&Blo[n * SA + kq * 8] =
                    __ldg((const uint4*)(pl + n * 128 + kb * 32 + kq * 8));
            }
            __syncthreads();

            #pragma unroll
            for (int kc = 0; kc < 2; kc++) {
                int k0 = kc * 16;
                uint32_t bh[8][2], bl[8][2];
                int brow = wn * 64 + (lane & 7);
                int bcol = k0 + ((lane & 8) ? 8 : 0);
                #pragma unroll
                for (int nt = 0; nt < 8; nt++) {
                    uint32_t boff = (uint32_t)((brow + nt * 8) * SA + bcol) * 2;
                    ldsm_x2(bh[nt][0], bh[nt][1], bhi_b + boff);
                    ldsm_x2(bl[nt][0], bl[nt][1], blo_b + boff);
                }
                uint32_t a[2][4];
                int arow = wm * 32 + (lane & 15);
                int acol = kb * 32 + k0 + ((lane & 16) ? 8 : 0);
                #pragma unroll
                for (int mt = 0; mt < 2; mt++)
                    ldsm_x4(a[mt][0], a[mt][1], a[mt][2], a[mt][3],
                            ahi_b + (uint32_t)((arow + mt * 16) * SAP + acol) * 2);
                #pragma unroll
                for (int mt = 0; mt < 2; mt++)
                    #pragma unroll
                    for (int nt = 0; nt < 8; nt++)
                        mma16816(acc[mt][nt], a[mt], bh[nt]);
                #pragma unroll
                for (int mt = 0; mt < 2; mt++)
                    #pragma unroll
                    for (int nt = 0; nt < 8; nt++)
                        mma16816(acc[mt][nt], a[mt], bl[nt]);
                #pragma unroll
                for (int mt = 0; mt < 2; mt++)
                    ldsm_x4(a[mt][0], a[mt][1], a[mt][2], a[mt][3],
                            alo_b + (uint32_t)((arow + mt * 16) * SAP + acol) * 2);
                #pragma unroll
                for (int mt = 0; mt < 2; mt++)
                    #pragma unroll
                    for (int nt = 0; nt < 8; nt++)
                        mma16816(acc[mt][nt], a[mt], bh[nt]);
            }
        }
        __syncthreads();   // MMA done reading A

        if (stage == 0) {
            #pragma unroll
            for (int mt = 0; mt < 2; mt++) {
                int r = wm * 32 + mt * 16 + g8;
                #pragma unroll
                for (int nt = 0; nt < 8; nt++) {
                    int c = wn * 64 + nt * 8 + tig * 2;
                    float2 bb = __ldg((const float2*)(pb1 + c));
                    float v0 = fmaxf(acc[mt][nt][0] + bb.x, 0.f);
                    float v1 = fmaxf(acc[mt][nt][1] + bb.y, 0.f);
                    float v2 = fmaxf(acc[mt][nt][2] + bb.x, 0.f);
                    float v3 = fmaxf(acc[mt][nt][3] + bb.y, 0.f);
                    unsigned short h0, l0, h1, l1, h2, l2, h3, l3;
                    split1(v0, h0, l0); split1(v1, h1, l1);
                    split1(v2, h2, l2); split1(v3, h3, l3);
                    Ahi[r * SAP + c] = h0;       Ahi[r * SAP + c + 1] = h1;
                    Alo[r * SAP + c] = l0;       Alo[r * SAP + c + 1] = l1;
                    Ahi[(r + 8) * SAP + c] = h2; Ahi[(r + 8) * SAP + c + 1] = h3;
                    Alo[(r + 8) * SAP + c] = l2; Alo[(r + 8) * SAP + c + 1] = l3;
                }
            }
        }
    }

    // final: out[p] = relu(acc + pb2) . pw3 + pb3
    {
        float s0 = 0.f, s1 = 0.f, s2 = 0.f, s3 = 0.f;
        #pragma unroll
        for (int nt = 0; nt < 8; nt++) {
            int c = wn * 64 + nt * 8 + tig * 2;
            float2 bb = __ldg((const float2*)(pb2 + c));
            float w0 = __ldg(pw3 + c);
            float w1 = __ldg(pw3 + c + 1);
            s0 += fmaxf(acc[0][nt][0] + bb.x, 0.f) * w0 + fmaxf(acc[0][nt][1] + bb.y, 0.f) * w1;
            s1 += fmaxf(acc[0][nt][2] + bb.x, 0.f) * w0 + fmaxf(acc[0][nt][3] + bb.y, 0.f) * w1;
            s2 += fmaxf(acc[1][nt][0] + bb.x, 0.f) * w0 + fmaxf(acc[1][nt][1] + bb.y, 0.f) * w1;
            s3 += fmaxf(acc[1][nt][2] + bb.x, 0.f) * w0 + fmaxf(acc[1][nt][3] + bb.y, 0.f) * w1;
        }
        #pragma unroll
        for (int dd = 1; dd < 4; dd <<= 1) {
            s0 += __shfl_xor_sync(0xffffffffu, s0, dd);
            s1 += __shfl_xor_sync(0xffffffffu, s1, dd);
            s2 += __shfl_xor_sync(0xffffffffu, s2, dd);
            s3 += __shfl_xor_sync(0xffffffffu, s3, dd);
        }
        if (tig == 0) {
            int r = wm * 32 + g8;
            red[r][wn]      = s0;
            red[r + 8][wn]  = s1;
            red[r + 16][wn] = s2;
            red[r + 24][wn] = s3;
        }
    }
    __syncthreads();
    if (t < 128 && p0 + t < PP)
        outp[p0 + t] = red[t][0] + red[t][1] + __ldg(pb3);
}

// ---------------------------------------------------------------------------
extern "C" void kernel_launch(void* const* d_in, const int* in_sizes, int n_in,
                              void* d_out, int out_size)
{
    const float* x     = (const float*)d_in[0];
    const int* src[3]  = {(const int*)d_in[1], (const int*)d_in[4], (const int*)d_in[7]};
    const int* dst[3]  = {(const int*)d_in[2], (const int*)d_in[5], (const int*)d_in[8]};
    const float* w[3]  = {(const float*)d_in[3], (const float*)d_in[6], (const float*)d_in[9]};
    const int* pos_src = (const int*)d_in[10];
    const int* pos_dst = (const int*)d_in[11];
    const int* neg_src = (const int*)d_in[12];
    const int* neg_dst = (const int*)d_in[13];
    const float* Wself[3]  = {(const float*)d_in[14], (const float*)d_in[17], (const float*)d_in[20]};
    const float* Wneigh[3] = {(const float*)d_in[15], (const float*)d_in[18], (const float*)d_in[21]};
    const float* bvec[3]   = {(const float*)d_in[16], (const float*)d_in[19], (const float*)d_in[22]};
    const float* pw1 = (const float*)d_in[23];
    const float* pb1 = (const float*)d_in[24];
    const float* pw2 = (const float*)d_in[25];
    const float* pb2 = (const float*)d_in[26];
    const float* pw3 = (const float*)d_in[27];
    const float* pb3 = (const float*)d_in[28];

    float* out = (float*)d_out;
    float* h_final = out + 2 * PP;

    void *hA_p, *hB_p;
    cudaGetSymbolAddress(&hA_p, g_hA);
    cudaGetSymbolAddress(&hB_p, g_hB);
    float* hA = (float*)hA_p;
    float* hB = (float*)hB_p;

    static bool attr_set = false;
    if (!attr_set) {
        cudaFuncSetAttribute(sage_node_mma, cudaFuncAttributeMaxDynamicSharedMemorySize, SMEM_NODE);
        cudaFuncSetAttribute(pred_mma, cudaFuncAttributeMaxDynamicSharedMemorySize, SMEM_PRED);
        attr_set = true;
    }

    const int edge_blocks = (EE * 32 + 255) / 256;
    const int node_blocks = (NN + 127) / 128;

    const float* layer_in[3]  = {x, hA, hB};
    float*       layer_out[3] = {hA, hB, h_final};

    convp_kernel<<<128, 256>>>(pw1, pw2);

    for (int l = 0; l < 3; l++) {
        convw_kernel<<<128, 256>>>(Wself[l], Wneigh[l]);
        edge_kernel<<<edge_blocks, 256>>>(src[l], dst[l], w[l], layer_in[l]);
        sage_node_mma<<<node_blocks, 256, SMEM_NODE>>>(layer_in[l], bvec[l],
                                                       layer_out[l], l < 2 ? 1 : 0);
    }

    pred_mma<<<2 * PB, 256, SMEM_PRED>>>(h_final, pos_src, pos_dst, neg_src, neg_dst,
                                         pb1, pb2, pw3, pb3, out);
}